// round 6
// baseline (speedup 1.0000x reference)
#include <cuda_runtime.h>
#include <cuda_fp16.h>
#include <math.h>
#include <stdint.h>

#define N_NODES 100000
#define N_EDGES 1600000
#define FNODE   64
#define FEDGE   32
#define EPSBN   1e-5f

// ---------------- device scratch --------------------------------------------
__device__ __align__(16) float  g_P[(size_t)N_NODES * 128];   // node @ W[0:64,:]   (int|upd)
__device__ __align__(16) float  g_Q[(size_t)N_NODES * 128];   // node @ W[64:128,:] (int|upd)
__device__ __align__(16) __half g_Yh[(size_t)N_EDGES * 128];  // pre-BN edge outputs, fp16
__device__ __align__(16) float  g_agg[(size_t)N_NODES * FNODE];
__device__ double g_sum[128];
__device__ double g_sumsq[128];
__device__ __align__(16) float  g_escale[128];
__device__ __align__(16) float  g_eshift[128];
__device__ double g_nsum[FNODE];
__device__ double g_nsumsq[FNODE];
__device__ float  g_nscale[FNODE];
__device__ float  g_nshift[FNODE];

// ---------------- helpers ----------------------------------------------------
__device__ __forceinline__ float sigf(float x) {
    return __fdividef(1.0f, 1.0f + __expf(-x));
}
__device__ __forceinline__ float spf(float x) {
    return fmaxf(x, 0.0f) + __logf(1.0f + __expf(-fabsf(x)));
}
__device__ __forceinline__ void red_add_v4(float* p, float4 v) {
    asm volatile("red.global.add.v4.f32 [%0], {%1, %2, %3, %4};"
                 :: "l"(p), "f"(v.x), "f"(v.y), "f"(v.z), "f"(v.w) : "memory");
}
__device__ __forceinline__ unsigned f2tf32(float f) {
    unsigned r;
    asm("cvt.rna.tf32.f32 %0, %1;" : "=r"(r) : "f"(f));
    return r;
}
__device__ __forceinline__ void mma_tf32(float& c0, float& c1, float& c2, float& c3,
                                         unsigned a0, unsigned a1, unsigned a2, unsigned a3,
                                         unsigned b0, unsigned b1) {
    asm("mma.sync.aligned.m16n8k8.row.col.f32.tf32.tf32.f32 "
        "{%0,%1,%2,%3}, {%4,%5,%6,%7}, {%8,%9}, {%0,%1,%2,%3};"
        : "+f"(c0), "+f"(c1), "+f"(c2), "+f"(c3)
        : "r"(a0), "r"(a1), "r"(a2), "r"(a3), "r"(b0), "r"(b1));
}

// ---------------- K1: P/Q node GEMMs -----------------------------------------
__global__ void __launch_bounds__(256)
k1_node_gemm(const float* __restrict__ node,
             const float* __restrict__ Wint,
             const float* __restrict__ Wupd) {
    __shared__ __align__(16) float sn[32 * 64];
    __shared__ __align__(16) float sw[64 * 128];
    const int tid = threadIdx.x;
    const int nbase = blockIdx.x * 32;

    for (int i = tid; i < 32 * 64; i += 256)
        sn[i] = node[(size_t)nbase * 64 + i];

    const int cg = tid & 31;
    const int ng = tid >> 5;

    for (int pass = 0; pass < 2; ++pass) {
        __syncthreads();
        for (int i = tid; i < 64 * 128; i += 256) {
            int k = i >> 7, c = i & 127;
            int krow = pass * 64 + k;
            sw[i] = (c < 64) ? Wint[krow * 64 + c] : Wupd[krow * 64 + (c - 64)];
        }
        __syncthreads();

        float4 acc[4];
#pragma unroll
        for (int i = 0; i < 4; ++i) acc[i] = make_float4(0.f, 0.f, 0.f, 0.f);

#pragma unroll 8
        for (int k = 0; k < 64; ++k) {
            float4 w = *(const float4*)&sw[k * 128 + 4 * cg];
#pragma unroll
            for (int i = 0; i < 4; ++i) {
                float nv = sn[(4 * ng + i) * 64 + k];
                acc[i].x += nv * w.x;
                acc[i].y += nv * w.y;
                acc[i].z += nv * w.z;
                acc[i].w += nv * w.w;
            }
        }
        float* dstp = (pass == 0) ? g_P : g_Q;
#pragma unroll
        for (int i = 0; i < 4; ++i)
            *(float4*)&dstp[(size_t)(nbase + 4 * ng + i) * 128 + 4 * cg] = acc[i];
    }
}

// ---------------- KA: tf32 mma edge GEMM + gather + fp16 spill ----------------
// Block = 128 edges. R = ef(128x32) @ Wc(32x128) on tensor pipe;
// epilogue adds gathered P[src]+Q[dst]+bias, spills fp16 Y.
#define APAD 36    // sA row pitch (bank-conflict-free a-frag loads)
#define WPAD 136   // sW row pitch (bank-conflict-free b-frag loads)
__global__ void __launch_bounds__(256)
kA_mma(const float* __restrict__ ef,
       const int* __restrict__ src,
       const int* __restrict__ dst,
       const float* __restrict__ Wint,
       const float* __restrict__ Wupd,
       const float* __restrict__ bint,
       const float* __restrict__ bupd) {
    __shared__ __align__(16) unsigned sA[128 * APAD];  // ef tile, tf32-rounded
    __shared__ __align__(16) unsigned sW[32 * WPAD];   // Wc, tf32-rounded
    __shared__ __align__(16) float sb[128];
    __shared__ int ssrc[128], sdst[128];

    const int tid = threadIdx.x;
    const size_t ebase = (size_t)blockIdx.x * 128;

    // stage ef (128x32 floats, contiguous) -> tf32 in sA
    {
        const float4* efv = (const float4*)(ef + ebase * 32);
#pragma unroll
        for (int it = 0; it < 4; ++it) {
            const int i = tid + it * 256;          // float4 index, 1024 total
            const float4 v = __ldcs(&efv[i]);
            const int row = i >> 3, col = (i & 7) * 4;
            unsigned* p = &sA[row * APAD + col];
            p[0] = f2tf32(v.x); p[1] = f2tf32(v.y);
            p[2] = f2tf32(v.z); p[3] = f2tf32(v.w);
        }
    }
    // stage Wc rows 128..159 (int cols 0-63 | upd 64-127), bias, indices
    for (int i = tid; i < 32 * 128; i += 256) {
        const int k = i >> 7, c = i & 127;
        const float w = (c < 64) ? Wint[(128 + k) * 64 + c] : Wupd[(128 + k) * 64 + (c - 64)];
        sW[k * WPAD + c] = f2tf32(w);
    }
    if (tid < 128) {
        sb[tid] = (tid < 64) ? bint[tid] : bupd[tid - 64];
        ssrc[tid] = src[ebase + tid];
        sdst[tid] = dst[ebase + tid];
    }
    __syncthreads();

    const int warp = tid >> 5, lane = tid & 31;
    const int g = lane >> 2, tig = lane & 3;
    const int row0 = warp * 16 + g, row1 = row0 + 8;

    float c0[16], c1[16], c2[16], c3[16];
#pragma unroll
    for (int nt = 0; nt < 16; ++nt) { c0[nt] = 0.f; c1[nt] = 0.f; c2[nt] = 0.f; c3[nt] = 0.f; }

#pragma unroll
    for (int kt = 0; kt < 4; ++kt) {
        const unsigned a0 = sA[row0 * APAD + kt * 8 + tig];
        const unsigned a1 = sA[row1 * APAD + kt * 8 + tig];
        const unsigned a2 = sA[row0 * APAD + kt * 8 + tig + 4];
        const unsigned a3 = sA[row1 * APAD + kt * 8 + tig + 4];
#pragma unroll
        for (int nt = 0; nt < 16; ++nt) {
            const unsigned b0 = sW[(kt * 8 + tig) * WPAD + nt * 8 + g];
            const unsigned b1 = sW[(kt * 8 + tig + 4) * WPAD + nt * 8 + g];
            mma_tf32(c0[nt], c1[nt], c2[nt], c3[nt], a0, a1, a2, a3, b0, b1);
        }
    }

    // epilogue: add gathered P+Q+bias, spill fp16
    const int s0 = ssrc[row0], d0 = sdst[row0];
    const int s1 = ssrc[row1], d1 = sdst[row1];
    const size_t e0 = ebase + row0, e1 = ebase + row1;

#pragma unroll
    for (int nt = 0; nt < 16; ++nt) {
        const int cc = nt * 8 + 2 * tig;
        const float2 bb = *(const float2*)&sb[cc];

        const float2 p0 = __ldg((const float2*)&g_P[(size_t)s0 * 128 + cc]);
        const float2 q0 = __ldg((const float2*)&g_Q[(size_t)d0 * 128 + cc]);
        const __half2 h0 = __floats2half2_rn(c0[nt] + p0.x + q0.x + bb.x,
                                             c1[nt] + p0.y + q0.y + bb.y);
        __stcs((unsigned*)&g_Yh[e0 * 128 + cc], *(const unsigned*)&h0);

        const float2 p1 = __ldg((const float2*)&g_P[(size_t)s1 * 128 + cc]);
        const float2 q1 = __ldg((const float2*)&g_Q[(size_t)d1 * 128 + cc]);
        const __half2 h1 = __floats2half2_rn(c2[nt] + p1.x + q1.x + bb.x,
                                             c3[nt] + p1.y + q1.y + bb.y);
        __stcs((unsigned*)&g_Yh[e1 * 128 + cc], *(const unsigned*)&h1);
    }
}

// ---------------- KS: column stats from fp16 Y --------------------------------
// grid = 800, 256 threads; thread handles 8 cols (16B chunk), 16 rows/block/iter.
__global__ void __launch_bounds__(256)
kS_stats() {
    const int tid = threadIdx.x;
    const int chunk = tid & 15;        // 16-byte chunk within the 256B row
    const int rsub = tid >> 4;         // 0..15
    const size_t rbase = (size_t)blockIdx.x * 2000;

    float s[8], q[8];
#pragma unroll
    for (int j = 0; j < 8; ++j) { s[j] = 0.f; q[j] = 0.f; }

    for (int it = 0; it < 125; ++it) {
        const size_t row = rbase + it * 16 + rsub;
        const uint4 v = __ldcs((const uint4*)&g_Yh[row * 128 + chunk * 8]);
        const unsigned u[4] = {v.x, v.y, v.z, v.w};
#pragma unroll
        for (int p = 0; p < 4; ++p) {
            const float2 f = __half22float2(*(const __half2*)&u[p]);
            s[2 * p]     += f.x;  q[2 * p]     += f.x * f.x;
            s[2 * p + 1] += f.y;  q[2 * p + 1] += f.y * f.y;
        }
    }

    __shared__ float ss[16][128];
    __shared__ float sq[16][128];
#pragma unroll
    for (int j = 0; j < 8; ++j) {
        ss[rsub][chunk * 8 + j] = s[j];
        sq[rsub][chunk * 8 + j] = q[j];
    }
    __syncthreads();
    if (tid < 128) {
        float a = 0.f;
#pragma unroll
        for (int r = 0; r < 16; ++r) a += ss[r][tid];
        atomicAdd(&g_sum[tid], (double)a);
    } else {
        const int c = tid - 128;
        float a = 0.f;
#pragma unroll
        for (int r = 0; r < 16; ++r) a += sq[r][c];
        atomicAdd(&g_sumsq[c], (double)a);
    }
}

// ---------------- K3: finalize edge BN ----------------------------------------
__global__ void k3_edge_bn(const float* __restrict__ gint,
                           const float* __restrict__ beint,
                           const float* __restrict__ gupd,
                           const float* __restrict__ beupd) {
    const int c = threadIdx.x;  // 128
    const double mu  = g_sum[c]   / (double)N_EDGES;
    const double var = g_sumsq[c] / (double)N_EDGES - mu * mu;
    const float gam = (c < 64) ? gint[c] : gupd[c - 64];
    const float bet = (c < 64) ? beint[c] : beupd[c - 64];
    const float sc = gam * rsqrtf((float)var + EPSBN);
    g_escale[c] = sc;
    g_eshift[c] = bet - (float)mu * sc;
}

// ---------------- KB: stream Yh, BN + act + scatter ----------------------------
__global__ void __launch_bounds__(256)
kB_apply(const int* __restrict__ dst) {
    const int tid = threadIdx.x;
    const int warp = tid >> 5, lane = tid & 31;
    const int s = lane & 15;
    const size_t e = (size_t)blockIdx.x * 16 + (size_t)warp * 2 + (lane >> 4);

    const uint2 gv = __ldcs((const uint2*)&g_Yh[e * 128 + 4 * s]);
    const uint2 uv = __ldcs((const uint2*)&g_Yh[e * 128 + 64 + 4 * s]);

    const float2 g01 = __half22float2(*(const __half2*)&gv.x);
    const float2 g23 = __half22float2(*(const __half2*)&gv.y);
    const float2 u01 = __half22float2(*(const __half2*)&uv.x);
    const float2 u23 = __half22float2(*(const __half2*)&uv.y);

    const float4 gs = *(const float4*)&g_escale[4 * s];
    const float4 gh = *(const float4*)&g_eshift[4 * s];
    const float4 us = *(const float4*)&g_escale[64 + 4 * s];
    const float4 uh = *(const float4*)&g_eshift[64 + 4 * s];

    float4 m;
    m.x = sigf(fmaf(g01.x, gs.x, gh.x)) * spf(fmaf(u01.x, us.x, uh.x));
    m.y = sigf(fmaf(g01.y, gs.y, gh.y)) * spf(fmaf(u01.y, us.y, uh.y));
    m.z = sigf(fmaf(g23.x, gs.z, gh.z)) * spf(fmaf(u23.x, us.z, uh.z));
    m.w = sigf(fmaf(g23.y, gs.w, gh.w)) * spf(fmaf(u23.y, us.w, uh.w));

    const int d = dst[e];
    red_add_v4(&g_agg[(size_t)d * 64 + 4 * s], m);
}

// ---------------- K5: node BN stats over agg -----------------------------------
__global__ void __launch_bounds__(256)
k5_node_stats() {
    const int tid = threadIdx.x;
    const int c = tid & 63;
    const int r0 = blockIdx.x * 512 + (tid >> 6);
    const int end = min((blockIdx.x + 1) * 512, N_NODES);

    float s = 0.f, ss = 0.f;
    for (int r = r0; r < end; r += 4) {
        float v = g_agg[(size_t)r * 64 + c];
        s += v;
        ss += v * v;
    }
    __shared__ float red[256], red2[256];
    red[tid] = s;
    red2[tid] = ss;
    __syncthreads();
    if (tid < 64) {
        float a  = red[tid]  + red[tid + 64]  + red[tid + 128]  + red[tid + 192];
        float b2 = red2[tid] + red2[tid + 64] + red2[tid + 128] + red2[tid + 192];
        atomicAdd(&g_nsum[tid], (double)a);
        atomicAdd(&g_nsumsq[tid], (double)b2);
    }
}

__global__ void k5b_node_bn(const float* __restrict__ gbn,
                            const float* __restrict__ bebn) {
    const int c = threadIdx.x;  // 64
    const double mu  = g_nsum[c]   / (double)N_NODES;
    const double var = g_nsumsq[c] / (double)N_NODES - mu * mu;
    const float sc = gbn[c] * rsqrtf((float)var + EPSBN);
    g_nscale[c] = sc;
    g_nshift[c] = bebn[c] - (float)mu * sc;
}

// ---------------- K6: final output ----------------------------------------------
__global__ void __launch_bounds__(256)
k6_out(const float* __restrict__ node, float* __restrict__ out) {
    const size_t i = (size_t)blockIdx.x * 256 + threadIdx.x;
    if (i >= (size_t)N_NODES * 64) return;
    const int c = (int)(i & 63);
    const float x = node[i] + g_agg[i] * g_nscale[c] + g_nshift[c];
    out[i] = fmaxf(x, 0.f) + log1pf(expf(-fabsf(x)));
}

// ---------------- launch ---------------------------------------------------------
extern "C" void kernel_launch(void* const* d_in, const int* in_sizes, int n_in,
                              void* d_out, int out_size) {
    const float* node  = (const float*)d_in[0];
    const float* edge  = (const float*)d_in[1];
    const int*   src   = (const int*)d_in[2];
    const int*   dst   = (const int*)d_in[3];
    const float* Wint  = (const float*)d_in[4];
    const float* bint  = (const float*)d_in[5];
    const float* gint  = (const float*)d_in[6];
    const float* beint = (const float*)d_in[7];
    const float* Wupd  = (const float*)d_in[8];
    const float* bupd  = (const float*)d_in[9];
    const float* gupd  = (const float*)d_in[10];
    const float* beupd = (const float*)d_in[11];
    const float* gbn   = (const float*)d_in[12];
    const float* bebn  = (const float*)d_in[13];
    float* out = (float*)d_out;

    void *pSum, *pSumsq, *pNsum, *pNsumsq, *pAgg;
    cudaGetSymbolAddress(&pSum,    g_sum);
    cudaGetSymbolAddress(&pSumsq,  g_sumsq);
    cudaGetSymbolAddress(&pNsum,   g_nsum);
    cudaGetSymbolAddress(&pNsumsq, g_nsumsq);
    cudaGetSymbolAddress(&pAgg,    g_agg);

    cudaMemsetAsync(pSum,    0, 128 * sizeof(double));
    cudaMemsetAsync(pSumsq,  0, 128 * sizeof(double));
    cudaMemsetAsync(pNsum,   0, FNODE * sizeof(double));
    cudaMemsetAsync(pNsumsq, 0, FNODE * sizeof(double));
    cudaMemsetAsync(pAgg,    0, (size_t)N_NODES * FNODE * sizeof(float));

    k1_node_gemm<<<N_NODES / 32, 256>>>(node, Wint, Wupd);
    kA_mma<<<N_EDGES / 128, 256>>>(edge, src, dst, Wint, Wupd, bint, bupd);
    kS_stats<<<800, 256>>>();
    k3_edge_bn<<<1, 128>>>(gint, beint, gupd, beupd);
    kB_apply<<<N_EDGES / 16, 256>>>(dst);
    k5_node_stats<<<(N_NODES + 511) / 512, 256>>>();
    k5b_node_bn<<<1, 64>>>(gbn, bebn);
    k6_out<<<((size_t)N_NODES * 64 + 255) / 256, 256>>>(node, out);
}